// round 16
// baseline (speedup 1.0000x reference)
#include <cuda_runtime.h>
#include <cuda_bf16.h>
#include <math.h>

// ---------------- scratch (static __device__, no allocation) ----------------
__device__ float g_feat1[1024 * 8 * 32 * 32];
__device__ float g_flat [1024 * 4096];
__device__ float g_h1   [1024 * 1024];
__device__ float g_last [1024 * 256];
__device__ float g_nrm  [1024 * 256];
__device__ float g_mv   [512];

// ---------------- XLA EmitFastTanh, NO FMA (mul/add like LLVM IR) -----------
__device__ __forceinline__ float xla_tanh(float x) {
    const float kMax = 7.90531110763549805f;
    float xc = fminf(fmaxf(x, -kMax), kMax);
    float x2 = __fmul_rn(xc, xc);
    float p = -2.76076847742355e-16f;
    p = __fadd_rn(__fmul_rn(p, x2),  2.00018790482477e-13f);
    p = __fadd_rn(__fmul_rn(p, x2), -8.60467152213735e-11f);
    p = __fadd_rn(__fmul_rn(p, x2),  5.12229709037114e-08f);
    p = __fadd_rn(__fmul_rn(p, x2),  1.48572235717979e-05f);
    p = __fadd_rn(__fmul_rn(p, x2),  6.37261928875436e-04f);
    p = __fadd_rn(__fmul_rn(p, x2),  4.89352455891786e-03f);
    float num = __fmul_rn(xc, p);
    float q =  1.19825839466702e-06f;
    q = __fadd_rn(__fmul_rn(q, x2),  1.18534705686654e-04f);
    q = __fadd_rn(__fmul_rn(q, x2),  2.26843463243900e-03f);
    q = __fadd_rn(__fmul_rn(q, x2),  4.89352518554385e-03f);
    float r = __fdiv_rn(num, q);
    return (fabsf(x) < 0.0004f) ? x : r;
}

// ---------------- conv1: k = (kh,kw) ascending FMA chain, bias after --------
__global__ void __launch_bounds__(256) conv1_pool(
    const float* __restrict__ x, const float* __restrict__ cw,
    const float* __restrict__ cb, float* __restrict__ out)
{
    __shared__ float sx[66 * 66];
    __shared__ float sw[8 * 9];
    __shared__ float sb[8];
    const int b = blockIdx.x;
    const float* xi = x + (size_t)b * 4096;

    for (int i = threadIdx.x; i < 66 * 66; i += 256) {
        int r = i / 66, c = i % 66;
        float v = 0.f;
        if (r >= 1 && r < 65 && c >= 1 && c < 65) v = xi[(r - 1) * 64 + (c - 1)];
        sx[i] = v;
    }
    if (threadIdx.x < 72) sw[threadIdx.x] = cw[threadIdx.x];
    if (threadIdx.x < 8)  sb[threadIdx.x] = cb[threadIdx.x];
    __syncthreads();

    for (int o = threadIdx.x; o < 8192; o += 256) {
        int oc = o >> 10, oh = (o >> 5) & 31, ow = o & 31;
        const float* w = &sw[oc * 9];
        float bias = sb[oc];
        float m = 0.f;
        int i0 = 2 * oh, j0 = 2 * ow;
        #pragma unroll
        for (int pi = 0; pi < 2; pi++) {
            #pragma unroll
            for (int pj = 0; pj < 2; pj++) {
                const float* p = &sx[(i0 + pi) * 66 + (j0 + pj)];
                float s = 0.f;
                #pragma unroll
                for (int kh = 0; kh < 3; kh++)
                    #pragma unroll
                    for (int kw = 0; kw < 3; kw++)
                        s = __fmaf_rn(p[kh * 66 + kw], w[kh * 3 + kw], s);
                s = __fadd_rn(s, bias);
                m = fmaxf(m, fmaxf(s, 0.f));
            }
        }
        out[(size_t)b * 8192 + o] = m;
    }
}

// ---------------- conv2: k = (kh,kw,ic) ascending, ic innermost, FMA --------
__global__ void __launch_bounds__(256) conv2_pool(
    const float* __restrict__ in, const float* __restrict__ cw,
    const float* __restrict__ cb, float* __restrict__ out)
{
    __shared__ float sx[8 * 34 * 34];
    __shared__ float sw[16 * 8 * 9];
    __shared__ float sb[16];
    const int b = blockIdx.x;
    const float* xi = in + (size_t)b * 8192;

    for (int i = threadIdx.x; i < 8 * 34 * 34; i += 256) {
        int ic = i / 1156, rem = i % 1156;
        int r = rem / 34, c = rem % 34;
        float v = 0.f;
        if (r >= 1 && r < 33 && c >= 1 && c < 33) v = xi[ic * 1024 + (r - 1) * 32 + (c - 1)];
        sx[i] = v;
    }
    for (int i = threadIdx.x; i < 1152; i += 256) sw[i] = cw[i];
    if (threadIdx.x < 16) sb[threadIdx.x] = cb[threadIdx.x];
    __syncthreads();

    const int oh = threadIdx.x >> 4, ow = threadIdx.x & 15;
    const int i0 = 2 * oh, j0 = 2 * ow;

    float patch[8][16];
    #pragma unroll
    for (int ic = 0; ic < 8; ic++)
        #pragma unroll
        for (int r = 0; r < 4; r++)
            #pragma unroll
            for (int c = 0; c < 4; c++)
                patch[ic][r * 4 + c] = sx[ic * 1156 + (i0 + r) * 34 + (j0 + c)];

    #pragma unroll
    for (int oc = 0; oc < 16; oc++) {
        float a00 = 0.f, a01 = 0.f, a10 = 0.f, a11 = 0.f;
        #pragma unroll
        for (int kh = 0; kh < 3; kh++) {
            #pragma unroll
            for (int kw = 0; kw < 3; kw++) {
                #pragma unroll
                for (int ic = 0; ic < 8; ic++) {
                    float w = sw[(oc * 8 + ic) * 9 + kh * 3 + kw];
                    a00 = __fmaf_rn(patch[ic][kh * 4 + kw],           w, a00);
                    a01 = __fmaf_rn(patch[ic][kh * 4 + kw + 1],       w, a01);
                    a10 = __fmaf_rn(patch[ic][(kh + 1) * 4 + kw],     w, a10);
                    a11 = __fmaf_rn(patch[ic][(kh + 1) * 4 + kw + 1], w, a11);
                }
            }
        }
        float bias = sb[oc];
        a00 = __fadd_rn(a00, bias); a01 = __fadd_rn(a01, bias);
        a10 = __fadd_rn(a10, bias); a11 = __fadd_rn(a11, bias);
        float m = fmaxf(fmaxf(fmaxf(a00, 0.f), fmaxf(a01, 0.f)),
                        fmaxf(fmaxf(a10, 0.f), fmaxf(a11, 0.f)));
        out[(size_t)b * 4096 + oc * 256 + threadIdx.x] = m;
    }
}

// ------- NT GEMM, FMA chain; partial-sum folds every FOLDK (template) -------
template <int BM, int BN, int TM, int TN, int FOLDK>
__global__ void __launch_bounds__(256) gemm_nt_tanh_kernel(
    const float* __restrict__ A, const float* __restrict__ B,
    const float* __restrict__ bias, float* __restrict__ C,
    int M, int N, int K)
{
    constexpr int BK = 16;
    constexpr int ATOT = BM * BK / 4;
    constexpr int BTOT = BN * BK / 4;
    constexpr int AV = (ATOT + 255) / 256;
    constexpr int BV = (BTOT + 255) / 256;

    __shared__ __align__(16) float As[2][BK][BM];
    __shared__ __align__(16) float Bs[2][BK][BN];

    const int tid = threadIdx.x;
    constexpr int NT = BN / TN;
    const int tcol = tid % NT;
    const int trow = tid / NT;
    const int m0 = blockIdx.y * BM;
    const int n0 = blockIdx.x * BN;

    #pragma unroll
    for (int v = 0; v < AV; v++) {
        int idx = tid + v * 256;
        if (ATOT % 256 == 0 || idx < ATOT) {
            int m = idx >> 2, kq = (idx & 3) * 4;
            float4 t = *(const float4*)(A + (size_t)(m0 + m) * K + kq);
            As[0][kq + 0][m] = t.x; As[0][kq + 1][m] = t.y;
            As[0][kq + 2][m] = t.z; As[0][kq + 3][m] = t.w;
        }
    }
    #pragma unroll
    for (int v = 0; v < BV; v++) {
        int idx = tid + v * 256;
        if (BTOT % 256 == 0 || idx < BTOT) {
            int n = idx >> 2, kq = (idx & 3) * 4;
            float4 t = *(const float4*)(B + (size_t)(n0 + n) * K + kq);
            Bs[0][kq + 0][n] = t.x; Bs[0][kq + 1][n] = t.y;
            Bs[0][kq + 2][n] = t.z; Bs[0][kq + 3][n] = t.w;
        }
    }
    __syncthreads();

    float acc[TM][TN], csum[TM][TN];
    #pragma unroll
    for (int i = 0; i < TM; i++)
        #pragma unroll
        for (int j = 0; j < TN; j++) { acc[i][j] = 0.f; csum[i][j] = 0.f; }

    const int nk = K / BK;
    int buf = 0;
    float4 ap[AV], bp[BV];

    for (int kt = 0; kt < nk; kt++) {
        if (kt + 1 < nk) {
            int k0 = (kt + 1) * BK;
            #pragma unroll
            for (int v = 0; v < AV; v++) {
                int idx = tid + v * 256;
                if (ATOT % 256 == 0 || idx < ATOT) {
                    int m = idx >> 2, kq = (idx & 3) * 4;
                    ap[v] = *(const float4*)(A + (size_t)(m0 + m) * K + k0 + kq);
                }
            }
            #pragma unroll
            for (int v = 0; v < BV; v++) {
                int idx = tid + v * 256;
                if (BTOT % 256 == 0 || idx < BTOT) {
                    int n = idx >> 2, kq = (idx & 3) * 4;
                    bp[v] = *(const float4*)(B + (size_t)(n0 + n) * K + k0 + kq);
                }
            }
        }
        #pragma unroll
        for (int k = 0; k < BK; k++) {
            float ra[TM], rb[TN];
            #pragma unroll
            for (int i = 0; i < TM; i += 4) {
                float4 t = *(const float4*)&As[buf][k][trow * TM + i];
                ra[i] = t.x; ra[i + 1] = t.y; ra[i + 2] = t.z; ra[i + 3] = t.w;
            }
            if constexpr (TN == 4) {
                float4 t = *(const float4*)&Bs[buf][k][tcol * 4];
                rb[0] = t.x; rb[1] = t.y; rb[2] = t.z; rb[3] = t.w;
            } else {
                float2 t = *(const float2*)&Bs[buf][k][tcol * 2];
                rb[0] = t.x; rb[1] = t.y;
            }
            #pragma unroll
            for (int i = 0; i < TM; i++)
                #pragma unroll
                for (int j = 0; j < TN; j++)
                    acc[i][j] = __fmaf_rn(ra[i], rb[j], acc[i][j]);
        }
        int kend = (kt + 1) * BK;
        if (kend % FOLDK == 0) {
            #pragma unroll
            for (int i = 0; i < TM; i++)
                #pragma unroll
                for (int j = 0; j < TN; j++) {
                    csum[i][j] = __fadd_rn(csum[i][j], acc[i][j]);
                    acc[i][j] = 0.f;
                }
        }
        if (kt + 1 < nk) {
            int nb = buf ^ 1;
            #pragma unroll
            for (int v = 0; v < AV; v++) {
                int idx = tid + v * 256;
                if (ATOT % 256 == 0 || idx < ATOT) {
                    int m = idx >> 2, kq = (idx & 3) * 4;
                    As[nb][kq + 0][m] = ap[v].x; As[nb][kq + 1][m] = ap[v].y;
                    As[nb][kq + 2][m] = ap[v].z; As[nb][kq + 3][m] = ap[v].w;
                }
            }
            #pragma unroll
            for (int v = 0; v < BV; v++) {
                int idx = tid + v * 256;
                if (BTOT % 256 == 0 || idx < BTOT) {
                    int n = idx >> 2, kq = (idx & 3) * 4;
                    Bs[nb][kq + 0][n] = bp[v].x; Bs[nb][kq + 1][n] = bp[v].y;
                    Bs[nb][kq + 2][n] = bp[v].z; Bs[nb][kq + 3][n] = bp[v].w;
                }
            }
            __syncthreads();
            buf = nb;
        }
    }
    #pragma unroll
    for (int i = 0; i < TM; i++)
        #pragma unroll
        for (int j = 0; j < TN; j++)
            csum[i][j] = __fadd_rn(csum[i][j], acc[i][j]);

    #pragma unroll
    for (int i = 0; i < TM; i++) {
        int m = m0 + trow * TM + i;
        #pragma unroll
        for (int j = 0; j < TN; j++) {
            int n = n0 + tcol * TN + j;
            C[(size_t)m * N + n] = xla_tanh(__fadd_rn(csum[i][j], bias[n]));
        }
    }
}

// ------- Gram + adjacency: plain ascending serial FMA chain (LOCKED) --------
__global__ void __launch_bounds__(256) gram_adj_kernel(
    const float* __restrict__ A, float* __restrict__ C)
{
    constexpr int BM = 64, BN = 64, BK = 16, TM = 4, TN = 4;
    constexpr int K = 256, N = 1024;
    __shared__ __align__(16) float As[2][BK][BM];
    __shared__ __align__(16) float Bs[2][BK][BN];

    const int tid = threadIdx.x;
    const int tcol = tid % 16;
    const int trow = tid / 16;
    const int m0 = blockIdx.y * BM;
    const int n0 = blockIdx.x * BN;

    {
        int m = tid >> 2, kq = (tid & 3) * 4;
        float4 t = *(const float4*)(A + (size_t)(m0 + m) * K + kq);
        As[0][kq + 0][m] = t.x; As[0][kq + 1][m] = t.y;
        As[0][kq + 2][m] = t.z; As[0][kq + 3][m] = t.w;
        float4 u = *(const float4*)(A + (size_t)(n0 + m) * K + kq);
        Bs[0][kq + 0][m] = u.x; Bs[0][kq + 1][m] = u.y;
        Bs[0][kq + 2][m] = u.z; Bs[0][kq + 3][m] = u.w;
    }
    __syncthreads();

    float s[TM][TN];
    #pragma unroll
    for (int i = 0; i < TM; i++)
        #pragma unroll
        for (int j = 0; j < TN; j++) s[i][j] = 0.f;

    const int nk = K / BK;
    int buf = 0;
    float4 ap, bp;

    for (int kt = 0; kt < nk; kt++) {
        if (kt + 1 < nk) {
            int k0 = (kt + 1) * BK;
            int m = tid >> 2, kq = (tid & 3) * 4;
            ap = *(const float4*)(A + (size_t)(m0 + m) * K + k0 + kq);
            bp = *(const float4*)(A + (size_t)(n0 + m) * K + k0 + kq);
        }
        #pragma unroll
        for (int k = 0; k < BK; k++) {
            float ra[TM], rb[TN];
            float4 t = *(const float4*)&As[buf][k][trow * TM];
            ra[0] = t.x; ra[1] = t.y; ra[2] = t.z; ra[3] = t.w;
            float4 u = *(const float4*)&Bs[buf][k][tcol * TN];
            rb[0] = u.x; rb[1] = u.y; rb[2] = u.z; rb[3] = u.w;
            #pragma unroll
            for (int i = 0; i < TM; i++)
                #pragma unroll
                for (int j = 0; j < TN; j++)
                    s[i][j] = __fmaf_rn(ra[i], rb[j], s[i][j]);
        }
        if (kt + 1 < nk) {
            int nb = buf ^ 1;
            int m = tid >> 2, kq = (tid & 3) * 4;
            As[nb][kq + 0][m] = ap.x; As[nb][kq + 1][m] = ap.y;
            As[nb][kq + 2][m] = ap.z; As[nb][kq + 3][m] = ap.w;
            Bs[nb][kq + 0][m] = bp.x; Bs[nb][kq + 1][m] = bp.y;
            Bs[nb][kq + 2][m] = bp.z; Bs[nb][kq + 3][m] = bp.w;
            __syncthreads();
            buf = nb;
        }
    }

    #pragma unroll
    for (int i = 0; i < TM; i++) {
        int m = m0 + trow * TM + i;
        #pragma unroll
        for (int j = 0; j < TN; j++) {
            int n = n0 + tcol * TN + j;
            float fid = __fmul_rn(s[i][j], s[i][j]);
            float a = fid >= 0.8f ? 1.0f : (fid >= 0.6f ? 0.5f : 0.0f);
            if (m == n) a = 0.0f;
            C[(size_t)m * N + n] = a;
        }
    }
}

// -------- row normalize: XLA:GPU row-reduce emulation ------------------------
// lane j partial = x[j] + x[j+32] + ... (8 elems, ascending), then
// shuffle-down tree: offsets 16, 8, 4, 2, 1. Emulated per-thread (1 thread/row).
__global__ void __launch_bounds__(256) rownorm_kernel(
    const float* __restrict__ last, float* __restrict__ nrm)
{
    int row = blockIdx.x * 256 + threadIdx.x;
    const float* p = last + (size_t)row * 256;
    float part[32];
    #pragma unroll
    for (int j = 0; j < 32; j++) {
        float s = 0.f;
        #pragma unroll
        for (int i = 0; i < 8; i++) {
            float v = p[j + i * 32];
            s = __fadd_rn(s, __fmul_rn(v, v));
        }
        part[j] = s;
    }
    #pragma unroll
    for (int off = 16; off >= 1; off >>= 1)
        #pragma unroll
        for (int j = 0; j < 16; j++)
            if (j < off) part[j] = __fadd_rn(part[j], part[j + off]);
    float den = __fadd_rn(__fsqrt_rn(part[0]), 1e-12f);
    float* q = nrm + (size_t)row * 256;
    for (int i = 0; i < 256; i++)
        q[i] = __fdiv_rn(p[i], den);
}

// -------- BN stats: XLA:GPU column-reduce emulation --------------------------
// 32 partials per column (rows r, r+32, ...), ascending, then tree combine.
__global__ void __launch_bounds__(256) bn_stats(
    const float* __restrict__ last, float* __restrict__ mv)
{
    const int j = threadIdx.x;
    float part[32];
    #pragma unroll
    for (int t = 0; t < 32; t++) {
        float s = 0.f;
        for (int r = t; r < 1024; r += 32)
            s = __fadd_rn(s, last[(size_t)r * 256 + j]);
        part[t] = s;
    }
    #pragma unroll
    for (int off = 16; off >= 1; off >>= 1)
        #pragma unroll
        for (int t = 0; t < 16; t++)
            if (t < off) part[t] = __fadd_rn(part[t], part[t + off]);
    float mean = __fdiv_rn(part[0], 1024.0f);

    #pragma unroll
    for (int t = 0; t < 32; t++) {
        float s = 0.f;
        for (int r = t; r < 1024; r += 32) {
            float d = __fsub_rn(last[(size_t)r * 256 + j], mean);
            s = __fadd_rn(s, __fmul_rn(d, d));
        }
        part[t] = s;
    }
    #pragma unroll
    for (int off = 16; off >= 1; off >>= 1)
        #pragma unroll
        for (int t = 0; t < 16; t++)
            if (t < off) part[t] = __fadd_rn(part[t], part[t + off]);
    mv[j] = mean;
    mv[256 + j] = __fdiv_rn(part[0], 1024.0f);
}

__global__ void __launch_bounds__(256) bn_apply(
    const float* __restrict__ last, const float* __restrict__ mv,
    const float* __restrict__ gamma, const float* __restrict__ beta,
    float* __restrict__ out)
{
    int idx = blockIdx.x * 256 + threadIdx.x;
    int j = idx & 255;
    float mean = mv[j], var = mv[256 + j];
    float r = __fdiv_rn(__fsub_rn(last[idx], mean), __fsqrt_rn(__fadd_rn(var, 1e-5f)));
    out[idx] = __fadd_rn(__fmul_rn(r, gamma[j]), beta[j]);
}

// ---------------- launch --------------------------------------------------
extern "C" void kernel_launch(void* const* d_in, const int* in_sizes, int n_in,
                              void* d_out, int out_size)
{
    const float* x     = (const float*)d_in[0];
    const float* cw1   = (const float*)d_in[1];
    const float* cb1   = (const float*)d_in[2];
    const float* cw2   = (const float*)d_in[3];
    const float* cb2   = (const float*)d_in[4];
    const float* w1    = (const float*)d_in[5];
    const float* b1    = (const float*)d_in[6];
    const float* w2    = (const float*)d_in[7];
    const float* b2    = (const float*)d_in[8];
    const float* gamma = (const float*)d_in[9];
    const float* beta  = (const float*)d_in[10];
    float* out = (float*)d_out;

    float *feat1, *flat, *h1, *last, *nrm, *mv;
    cudaGetSymbolAddress((void**)&feat1, g_feat1);
    cudaGetSymbolAddress((void**)&flat,  g_flat);
    cudaGetSymbolAddress((void**)&h1,    g_h1);
    cudaGetSymbolAddress((void**)&last,  g_last);
    cudaGetSymbolAddress((void**)&nrm,   g_nrm);
    cudaGetSymbolAddress((void**)&mv,    g_mv);

    conv1_pool<<<1024, 256>>>(x, cw1, cb1, feat1);
    conv2_pool<<<1024, 256>>>(feat1, cw2, cb2, flat);

    gemm_nt_tanh_kernel<128, 64, 8, 4, 512><<<dim3(16, 8), 256>>>(flat, w1, b1, h1, 1024, 1024, 4096);
    gemm_nt_tanh_kernel<64, 32, 4, 2, 512><<<dim3(8, 16), 256>>>(h1, w2, b2, last, 1024, 256, 1024);

    rownorm_kernel<<<4, 256>>>(last, nrm);

    gram_adj_kernel<<<dim3(16, 16), 256>>>(nrm, out + 1024 * 256);

    bn_stats<<<1, 256>>>(last, mv);
    bn_apply<<<1024, 256>>>(last, mv, gamma, beta, out);
}